// round 13
// baseline (speedup 1.0000x reference)
#include <cuda_runtime.h>
#include <cuda_bf16.h>
#include <math_constants.h>
#include <cstdint>

// Causal attention B=4 L=4096 D=128 fp32 via mma.sync bf16 hi/lo split (3-term).
// Pass 1: cvt fp32 -> bf16 hi/lo (Q pre-scaled by 1/sqrt(128)).
// Pass 2: FA2 split-K. BQ=128, 4 warps: warp w owns q-rows [32w,32w+32) as two
//   16-row A-tiles, so every K/V fragment is ldsm'd once and used twice
//   (halves smem crossbar traffic per unit of work -> tensor-bound).
//   K/V double-buffered via cp.async (192KB smem). Chunks of <=16 k-tiles,
//   LPT order, 320 CTAs; partials (O, m, l) to global scratch.
// Pass 3: combine kernel merges <=4 partials per row.

namespace {
constexpr int SEQ = 4096, HD = 128, NB = 4;
constexpr int BQ = 128, BK = 64;
constexpr int NQT = SEQ / BQ;  // 32
constexpr int NTH = 128;
constexpr int CHUNK = 16;  // k-tiles per chunk
constexpr size_t TELEM = (size_t)NB * SEQ * HD;

// smem: Q hi/lo 64KB, then two 64KB K/V buffers (KH,KL,VH,VL each 16KB).
constexpr int SM_QH = 0, SM_QL = 32768;
constexpr int SM_BUF0 = 65536;
constexpr int BUF_STRIDE = 65536;
constexpr int SMEM_BYTES = SM_BUF0 + 2 * BUF_STRIDE;  // 196608

// chunks per q-tile qt: ceil((2qt+2)/16) = (2qt+17)>>4 (1..4)
constexpr int NSLOT = NB * NQT * 4;  // 512
}  // namespace

__device__ __nv_bfloat16 g_hi[3][TELEM];  // 0=K, 1=Q(scaled), 2=V
__device__ __nv_bfloat16 g_lo[3][TELEM];
__device__ float g_opart[NSLOT][BQ * HD];  // unnormalized partial O (33.5MB)
__device__ float2 g_mlpart[NSLOT][BQ];     // per-row (m, l)

namespace {

__device__ __forceinline__ unsigned smem_u32(const void* p) {
  unsigned a;
  asm("{ .reg .u64 t; cvta.to.shared.u64 t, %1; cvt.u32.u64 %0, t; }" : "=r"(a) : "l"(p));
  return a;
}

__device__ __forceinline__ void splitpk(float x, float y, unsigned& hi, unsigned& lo) {
  __nv_bfloat162 h = __floats2bfloat162_rn(x, y);
  hi = *reinterpret_cast<unsigned*>(&h);
  __nv_bfloat162 l = __floats2bfloat162_rn(x - __bfloat162float(h.x),
                                           y - __bfloat162float(h.y));
  lo = *reinterpret_cast<unsigned*>(&l);
}

__device__ __forceinline__ void ldsm4(unsigned* r, unsigned a) {
  asm volatile("ldmatrix.sync.aligned.m8n8.x4.shared.b16 {%0,%1,%2,%3}, [%4];"
               : "=r"(r[0]), "=r"(r[1]), "=r"(r[2]), "=r"(r[3]) : "r"(a));
}

__device__ __forceinline__ void ldsm4t(unsigned* r, unsigned a) {
  asm volatile("ldmatrix.sync.aligned.m8n8.x4.trans.shared.b16 {%0,%1,%2,%3}, [%4];"
               : "=r"(r[0]), "=r"(r[1]), "=r"(r[2]), "=r"(r[3]) : "r"(a));
}

__device__ __forceinline__ void mma16816(float* d, const unsigned* a, unsigned b0,
                                         unsigned b1) {
  asm volatile(
      "mma.sync.aligned.m16n8k16.row.col.f32.bf16.bf16.f32 "
      "{%0,%1,%2,%3}, {%4,%5,%6,%7}, {%8,%9}, {%0,%1,%2,%3};"
      : "+f"(d[0]), "+f"(d[1]), "+f"(d[2]), "+f"(d[3])
      : "r"(a[0]), "r"(a[1]), "r"(a[2]), "r"(a[3]), "r"(b0), "r"(b1));
}

// Synchronous copy of a ROWS x 128 bf16 tile into swizzled smem (128 threads).
template <int ROWS>
__device__ __forceinline__ void copy_tileN(char* sm, int off, const __nv_bfloat16* g,
                                           int tid) {
  const uint4* g4 = (const uint4*)g;
#pragma unroll
  for (int it = 0; it < ROWS * 16 / NTH; ++it) {
    const int c16 = it * NTH + tid;
    const int row = c16 >> 4, c = c16 & 15;
    const uint4 v = g4[c16];
    *(uint4*)(sm + off + row * 256 + ((c ^ (row & 7)) << 4)) = v;
  }
}

// Async copy of a 64x128 bf16 tile into swizzled smem (128 threads).
__device__ __forceinline__ void copy_tile_async(unsigned dst, const __nv_bfloat16* g,
                                                int tid) {
  const uint4* g4 = (const uint4*)g;
#pragma unroll
  for (int it = 0; it < 8; ++it) {
    const int c16 = it * NTH + tid;
    const int row = c16 >> 4, c = c16 & 15;
    const unsigned a = dst + row * 256 + ((c ^ (row & 7)) << 4);
    asm volatile("cp.async.cg.shared.global [%0], [%1], 16;" :: "r"(a), "l"(g4 + c16)
                 : "memory");
  }
}
}  // namespace

// ---- Pass 1: fp32 -> bf16 hi/lo (Q scaled by 1/sqrt(HD)) ----
__global__ void cvt_kernel(const float* __restrict__ K, const float* __restrict__ Q,
                           const float* __restrict__ V) {
  constexpr int N4 = (int)(TELEM / 4);
  const int stride = gridDim.x * blockDim.x;
  const float qscale = 0.088388347648318447f;  // 1/sqrt(128)
  for (int idx = blockIdx.x * blockDim.x + threadIdx.x; idx < 3 * N4; idx += stride) {
    const int t = idx / N4, e = idx - t * N4;
    const float* src = (t == 0) ? K : ((t == 1) ? Q : V);
    float4 v = ((const float4*)src)[e];
    if (t == 1) {
      v.x *= qscale; v.y *= qscale; v.z *= qscale; v.w *= qscale;
    }
    unsigned h0, l0, h1, l1;
    splitpk(v.x, v.y, h0, l0);
    splitpk(v.z, v.w, h1, l1);
    ((uint2*)g_hi[t])[e] = make_uint2(h0, h1);
    ((uint2*)g_lo[t])[e] = make_uint2(l0, l1);
  }
}

// ---- Pass 2: flash attention chunk kernel ----
__global__ __launch_bounds__(NTH, 1)
void fa_mma_kernel() {
  extern __shared__ char sm[];
  const unsigned smb = smem_u32(sm);
  const int tid = threadIdx.x, lane = tid & 31, w = tid >> 5;
  const int g = lane >> 3, l7 = lane & 7, quad = lane >> 2, qlane = lane & 3;

  // decode chunk: batches interleaved, q-tiles descending (LPT order)
  const int b = blockIdx.x & 3;
  int ci = blockIdx.x >> 2;
  int qt = 0, c = 0;
  for (int t = NQT - 1; t >= 0; --t) {
    const int n = (2 * t + 17) >> 4;
    if (ci < n) { qt = t; c = ci; break; }
    ci -= n;
  }
  const int q0 = qt * BQ;
  const int ktb = c * CHUNK;
  const int kte = min(ktb + CHUNK, 2 * qt + 2);

  const __nv_bfloat16* Kh = g_hi[0] + (size_t)b * SEQ * HD;
  const __nv_bfloat16* Kl = g_lo[0] + (size_t)b * SEQ * HD;
  const __nv_bfloat16* Qh = g_hi[1] + (size_t)b * SEQ * HD;
  const __nv_bfloat16* Ql = g_lo[1] + (size_t)b * SEQ * HD;
  const __nv_bfloat16* Vh = g_hi[2] + (size_t)b * SEQ * HD;
  const __nv_bfloat16* Vl = g_lo[2] + (size_t)b * SEQ * HD;

  // ldmatrix per-lane row/chunk offsets
  const int rowAl = ((g & 1) << 3) + l7;         // A (Q)
  const int cAoff = g >> 1;
  const int rowBl = (((g >> 1) & 1) << 3) + l7;  // B (K)
  const int cBoff = g & 1;
  const int rowVl = ((g & 1) << 3) + l7;         // V (trans)
  const int cVoff = g >> 1;

  copy_tileN<128>(sm, SM_QH, Qh + (size_t)q0 * HD, tid);
  copy_tileN<128>(sm, SM_QL, Ql + (size_t)q0 * HD, tid);

  // prologue: async-load first k-tile into buffer 0
  unsigned buf = 0;
  {
    const size_t nk = (size_t)ktb * BK * HD;
    const unsigned nb = smb + SM_BUF0;
    copy_tile_async(nb, Kh + nk, tid);
    copy_tile_async(nb + 16384u, Kl + nk, tid);
    copy_tile_async(nb + 32768u, Vh + nk, tid);
    copy_tile_async(nb + 49152u, Vl + nk, tid);
    asm volatile("cp.async.commit_group;" ::: "memory");
  }

  float o[2][16][4];
#pragma unroll
  for (int rg = 0; rg < 2; ++rg)
#pragma unroll
    for (int n = 0; n < 16; ++n)
#pragma unroll
      for (int e = 0; e < 4; ++e) o[rg][n][e] = 0.f;
  float m0[2] = {-CUDART_INF_F, -CUDART_INF_F}, m1[2] = {-CUDART_INF_F, -CUDART_INF_F};
  float l0[2] = {0.f, 0.f}, l1[2] = {0.f, 0.f};

  for (int kt = ktb; kt < kte; ++kt) {
    asm volatile("cp.async.wait_group 0;" ::: "memory");
    __syncthreads();  // buffer ready; all warps past prior reads

    if (kt + 1 < kte) {  // prefetch next tile into the other buffer
      const unsigned nb = smb + SM_BUF0 + (buf ^ 1u) * (unsigned)BUF_STRIDE;
      const size_t nk = (size_t)(kt + 1) * BK * HD;
      copy_tile_async(nb, Kh + nk, tid);
      copy_tile_async(nb + 16384u, Kl + nk, tid);
      copy_tile_async(nb + 32768u, Vh + nk, tid);
      copy_tile_async(nb + 49152u, Vl + nk, tid);
      asm volatile("cp.async.commit_group;" ::: "memory");
    }
    const unsigned kb = smb + SM_BUF0 + buf * (unsigned)BUF_STRIDE;
    buf ^= 1u;

    // ---- S = Qh*Kh + Qh*Kl + Ql*Kh for both 16-row A-tiles ----
    float s[2][8][4];
#pragma unroll
    for (int rg = 0; rg < 2; ++rg)
#pragma unroll
      for (int n = 0; n < 8; ++n)
#pragma unroll
        for (int e = 0; e < 4; ++e) s[rg][n][e] = 0.f;

    const unsigned arow = smb + SM_QH + (unsigned)(32 * w + rowAl) * 256u;
#pragma unroll
    for (int ks = 0; ks < 8; ++ks) {
      unsigned ah[2][4], al[2][4];
      const unsigned ca = (unsigned)(((2 * ks + cAoff) ^ l7) << 4);
#pragma unroll
      for (int rg = 0; rg < 2; ++rg) {
        ldsm4(ah[rg], arow + (unsigned)rg * 4096u + ca);
        ldsm4(al[rg], arow + (unsigned)rg * 4096u + 32768u + ca);
      }
      const unsigned cb = (unsigned)(((2 * ks + cBoff) ^ l7) << 4);
#pragma unroll
      for (int t = 0; t < 4; ++t) {
        unsigned bh[4], bl[4];
        const unsigned kaddr = kb + (unsigned)(t * 16 + rowBl) * 256u + cb;
        ldsm4(bh, kaddr);
        ldsm4(bl, kaddr + 16384u);
#pragma unroll
        for (int rg = 0; rg < 2; ++rg) {  // B frags used twice
          mma16816(s[rg][2 * t], ah[rg], bh[0], bh[1]);
          mma16816(s[rg][2 * t + 1], ah[rg], bh[2], bh[3]);
          mma16816(s[rg][2 * t], ah[rg], bl[0], bl[1]);
          mma16816(s[rg][2 * t + 1], ah[rg], bl[2], bl[3]);
          mma16816(s[rg][2 * t], al[rg], bh[0], bh[1]);
          mma16816(s[rg][2 * t + 1], al[rg], bh[2], bh[3]);
        }
      }
    }

    // ---- causal mask: key offset within q-tile = (kt-2qt)*64 (last 2 tiles) ----
    if (kt >= 2 * qt) {
      const int off = (kt - 2 * qt) * 64;
#pragma unroll
      for (int rg = 0; rg < 2; ++rg) {
        const int r0l = 32 * w + 16 * rg + quad;
#pragma unroll
        for (int n = 0; n < 8; ++n) {
          const int c0 = off + 8 * n + 2 * qlane;
          if (c0 > r0l) s[rg][n][0] = -CUDART_INF_F;
          if (c0 + 1 > r0l) s[rg][n][1] = -CUDART_INF_F;
          if (c0 > r0l + 8) s[rg][n][2] = -CUDART_INF_F;
          if (c0 + 1 > r0l + 8) s[rg][n][3] = -CUDART_INF_F;
        }
      }
    }

    // ---- online softmax (quad-local, per row group) ----
#pragma unroll
    for (int rg = 0; rg < 2; ++rg) {
      float mx0 = -CUDART_INF_F, mx1 = -CUDART_INF_F;
#pragma unroll
      for (int n = 0; n < 8; ++n) {
        mx0 = fmaxf(mx0, fmaxf(s[rg][n][0], s[rg][n][1]));
        mx1 = fmaxf(mx1, fmaxf(s[rg][n][2], s[rg][n][3]));
      }
      mx0 = fmaxf(mx0, __shfl_xor_sync(0xffffffffu, mx0, 1));
      mx0 = fmaxf(mx0, __shfl_xor_sync(0xffffffffu, mx0, 2));
      mx1 = fmaxf(mx1, __shfl_xor_sync(0xffffffffu, mx1, 1));
      mx1 = fmaxf(mx1, __shfl_xor_sync(0xffffffffu, mx1, 2));
      const float m0n = fmaxf(m0[rg], mx0), m1n = fmaxf(m1[rg], mx1);
      const float a0 = __expf(m0[rg] - m0n), a1 = __expf(m1[rg] - m1n);
      float s0 = 0.f, s1 = 0.f;
#pragma unroll
      for (int n = 0; n < 8; ++n) {
        s[rg][n][0] = __expf(s[rg][n][0] - m0n);
        s[rg][n][1] = __expf(s[rg][n][1] - m0n);
        s[rg][n][2] = __expf(s[rg][n][2] - m1n);
        s[rg][n][3] = __expf(s[rg][n][3] - m1n);
        s0 += s[rg][n][0] + s[rg][n][1];
        s1 += s[rg][n][2] + s[rg][n][3];
      }
      s0 += __shfl_xor_sync(0xffffffffu, s0, 1);
      s0 += __shfl_xor_sync(0xffffffffu, s0, 2);
      s1 += __shfl_xor_sync(0xffffffffu, s1, 1);
      s1 += __shfl_xor_sync(0xffffffffu, s1, 2);
      l0[rg] = l0[rg] * a0 + s0;
      l1[rg] = l1[rg] * a1 + s1;
      m0[rg] = m0n;
      m1[rg] = m1n;
#pragma unroll
      for (int n = 0; n < 16; ++n) {
        o[rg][n][0] *= a0;
        o[rg][n][1] *= a0;
        o[rg][n][2] *= a1;
        o[rg][n][3] *= a1;
      }
    }

    // ---- O += Ph*Vh + Ph*Vl + Pl*Vh (V frags used twice) ----
#pragma unroll
    for (int ks = 0; ks < 4; ++ks) {
      unsigned ah[2][4], al[2][4];
#pragma unroll
      for (int rg = 0; rg < 2; ++rg) {
        splitpk(s[rg][2 * ks][0], s[rg][2 * ks][1], ah[rg][0], al[rg][0]);
        splitpk(s[rg][2 * ks][2], s[rg][2 * ks][3], ah[rg][1], al[rg][1]);
        splitpk(s[rg][2 * ks + 1][0], s[rg][2 * ks + 1][1], ah[rg][2], al[rg][2]);
        splitpk(s[rg][2 * ks + 1][2], s[rg][2 * ks + 1][3], ah[rg][3], al[rg][3]);
      }
#pragma unroll
      for (int u = 0; u < 8; ++u) {
        unsigned vh[4], vl[4];
        const unsigned vaddr = kb + 32768u + (unsigned)(16 * ks + rowVl) * 256u +
                               (unsigned)(((2 * u + cVoff) ^ l7) << 4);
        ldsm4t(vh, vaddr);
        ldsm4t(vl, vaddr + 16384u);
#pragma unroll
        for (int rg = 0; rg < 2; ++rg) {
          mma16816(o[rg][2 * u], ah[rg], vh[0], vh[1]);
          mma16816(o[rg][2 * u + 1], ah[rg], vh[2], vh[3]);
          mma16816(o[rg][2 * u], ah[rg], vl[0], vl[1]);
          mma16816(o[rg][2 * u + 1], ah[rg], vl[2], vl[3]);
          mma16816(o[rg][2 * u], al[rg], vh[0], vh[1]);
          mma16816(o[rg][2 * u + 1], al[rg], vh[2], vh[3]);
        }
      }
    }
  }  // kt

  // ---- epilogue: write unnormalized partial O + (m, l) to scratch ----
  const int slot = ((b * NQT + qt) << 2) + c;
  float* op = g_opart[slot];
#pragma unroll
  for (int rg = 0; rg < 2; ++rg) {
    const int r0l = 32 * w + 16 * rg + quad;
#pragma unroll
    for (int n = 0; n < 16; ++n) {
      const int col = 8 * n + 2 * qlane;
      *(float2*)(op + r0l * HD + col) = make_float2(o[rg][n][0], o[rg][n][1]);
      *(float2*)(op + (r0l + 8) * HD + col) = make_float2(o[rg][n][2], o[rg][n][3]);
    }
    if (qlane == 0) {
      g_mlpart[slot][r0l] = make_float2(m0[rg], l0[rg]);
      g_mlpart[slot][r0l + 8] = make_float2(m1[rg], l1[rg]);
    }
  }
}

// ---- Pass 3: combine partials (one warp per output row) ----
__global__ __launch_bounds__(256)
void combine_kernel(float* __restrict__ Og) {
  const int row = (blockIdx.x * blockDim.x + threadIdx.x) >> 5;  // 0..16383
  const int lane = threadIdx.x & 31;
  const int b = row >> 12, r = row & 4095;
  const int qt = r >> 7, rr = r & 127;
  const int nc = (2 * qt + 17) >> 4;
  const int slot0 = (b * NQT + qt) << 2;

  float m[4], l[4];
  float mstar = -CUDART_INF_F;
#pragma unroll
  for (int c = 0; c < 4; ++c) {
    if (c < nc) {
      const float2 ml = g_mlpart[slot0 + c][rr];
      m[c] = ml.x;
      l[c] = ml.y;
      mstar = fmaxf(mstar, ml.x);
    }
  }
  float denom = 0.f, wgt[4];
#pragma unroll
  for (int c = 0; c < 4; ++c) {
    if (c < nc) {
      wgt[c] = __expf(m[c] - mstar);
      denom += wgt[c] * l[c];
    }
  }
  float4 acc = make_float4(0.f, 0.f, 0.f, 0.f);
#pragma unroll
  for (int c = 0; c < 4; ++c) {
    if (c < nc) {
      const float4 v = *(const float4*)(g_opart[slot0 + c] + rr * HD + lane * 4);
      acc.x += wgt[c] * v.x;
      acc.y += wgt[c] * v.y;
      acc.z += wgt[c] * v.z;
      acc.w += wgt[c] * v.w;
    }
  }
  const float inv = 1.f / denom;
  acc.x *= inv; acc.y *= inv; acc.z *= inv; acc.w *= inv;
  *(float4*)(Og + ((size_t)b * SEQ + r) * HD + lane * 4) = acc;
}

extern "C" void kernel_launch(void* const* d_in, const int* in_sizes, int n_in,
                              void* d_out, int out_size) {
  const float* K = (const float*)d_in[0];
  const float* Q = (const float*)d_in[1];
  const float* V = (const float*)d_in[2];
  float* O = (float*)d_out;

  cvt_kernel<<<2048, 256>>>(K, Q, V);

  cudaFuncSetAttribute(fa_mma_kernel, cudaFuncAttributeMaxDynamicSharedMemorySize,
                       SMEM_BYTES);
  // chunks per batch: sum over qt of (2qt+17)>>4 = 80; batches interleaved.
  fa_mma_kernel<<<80 * NB, NTH, SMEM_BYTES>>>();

  combine_kernel<<<(NB * SEQ * 32) / 256, 256>>>(O);
}

// round 14
// speedup vs baseline: 1.0980x; 1.0980x over previous
#include <cuda_runtime.h>
#include <cuda_bf16.h>
#include <math_constants.h>
#include <cstdint>

// Causal attention B=4 L=4096 D=128 fp32 via mma.sync bf16 hi/lo split (3-term).
// Pass 1: cvt fp32 -> bf16 hi/lo (Q pre-scaled by 1/sqrt(128)).
// Pass 2: FA2 split-K. BQ=64, 4 warps, BK=32 k-tiles DOUBLE-BUFFERED via
//   cp.async within 96KB smem -> 2 CTAs/SM co-resident AND loads overlapped.
//   Chunks of 1024 keys (32 k32-tiles), LPT order, 640 CTAs; partials
//   (O, m, l) to global scratch.
// Pass 3: combine kernel merges <=4 partials per row.

namespace {
constexpr int SEQ = 4096, HD = 128, NB = 4;
constexpr int BQ = 64, BK = 32;
constexpr int NTH = 128;
constexpr int CHUNK32 = 32;  // 32-key tiles per chunk (1024 keys)
constexpr size_t TELEM = (size_t)NB * SEQ * HD;

// smem: Q hi/lo 32KB + two 32KB K/V buffers (KH 0, KL 8K, VH 16K, VL 24K).
constexpr int SM_QH = 0, SM_QL = 16384;
constexpr int SM_BUF0 = 32768;
constexpr int BUF_STRIDE = 32768;
constexpr int SMEM_BYTES = SM_BUF0 + 2 * BUF_STRIDE;  // 98304 -> 2 CTAs/SM

// chunks per 64-row q-tile qt: (qt>>4)+1 (1..4). slots = (b*64+qt)*4 + c.
constexpr int NSLOT = NB * 64 * 4;  // 1024
}  // namespace

__device__ __nv_bfloat16 g_hi[3][TELEM];  // 0=K, 1=Q(scaled), 2=V
__device__ __nv_bfloat16 g_lo[3][TELEM];
__device__ float g_opart[NSLOT][BQ * HD];  // unnormalized partial O (34MB)
__device__ float2 g_mlpart[NSLOT][BQ];     // per-row (m, l)

namespace {

__device__ __forceinline__ unsigned smem_u32(const void* p) {
  unsigned a;
  asm("{ .reg .u64 t; cvta.to.shared.u64 t, %1; cvt.u32.u64 %0, t; }" : "=r"(a) : "l"(p));
  return a;
}

__device__ __forceinline__ void splitpk(float x, float y, unsigned& hi, unsigned& lo) {
  __nv_bfloat162 h = __floats2bfloat162_rn(x, y);
  hi = *reinterpret_cast<unsigned*>(&h);
  __nv_bfloat162 l = __floats2bfloat162_rn(x - __bfloat162float(h.x),
                                           y - __bfloat162float(h.y));
  lo = *reinterpret_cast<unsigned*>(&l);
}

__device__ __forceinline__ void ldsm4(unsigned* r, unsigned a) {
  asm volatile("ldmatrix.sync.aligned.m8n8.x4.shared.b16 {%0,%1,%2,%3}, [%4];"
               : "=r"(r[0]), "=r"(r[1]), "=r"(r[2]), "=r"(r[3]) : "r"(a));
}

__device__ __forceinline__ void ldsm4t(unsigned* r, unsigned a) {
  asm volatile("ldmatrix.sync.aligned.m8n8.x4.trans.shared.b16 {%0,%1,%2,%3}, [%4];"
               : "=r"(r[0]), "=r"(r[1]), "=r"(r[2]), "=r"(r[3]) : "r"(a));
}

__device__ __forceinline__ void mma16816(float* d, const unsigned* a, unsigned b0,
                                         unsigned b1) {
  asm volatile(
      "mma.sync.aligned.m16n8k16.row.col.f32.bf16.bf16.f32 "
      "{%0,%1,%2,%3}, {%4,%5,%6,%7}, {%8,%9}, {%0,%1,%2,%3};"
      : "+f"(d[0]), "+f"(d[1]), "+f"(d[2]), "+f"(d[3])
      : "r"(a[0]), "r"(a[1]), "r"(a[2]), "r"(a[3]), "r"(b0), "r"(b1));
}

// Synchronous copy of a 64x128 bf16 tile into swizzled smem (128 threads).
__device__ __forceinline__ void copy_tile64(char* sm, int off, const __nv_bfloat16* g,
                                            int tid) {
  const uint4* g4 = (const uint4*)g;
#pragma unroll
  for (int it = 0; it < 8; ++it) {
    const int c16 = it * NTH + tid;
    const int row = c16 >> 4, c = c16 & 15;
    const uint4 v = g4[c16];
    *(uint4*)(sm + off + row * 256 + ((c ^ (row & 7)) << 4)) = v;
  }
}

// Async copy of a 32x128 bf16 tile into swizzled smem (128 threads).
__device__ __forceinline__ void copy_tile_async32(unsigned dst, const __nv_bfloat16* g,
                                                  int tid) {
  const uint4* g4 = (const uint4*)g;
#pragma unroll
  for (int it = 0; it < 4; ++it) {
    const int c16 = it * NTH + tid;  // 0..511
    const int row = c16 >> 4, c = c16 & 15;
    const unsigned a = dst + row * 256 + ((c ^ (row & 7)) << 4);
    asm volatile("cp.async.cg.shared.global [%0], [%1], 16;" :: "r"(a), "l"(g4 + c16)
                 : "memory");
  }
}
}  // namespace

// ---- Pass 1: fp32 -> bf16 hi/lo (Q scaled by 1/sqrt(HD)) ----
__global__ void cvt_kernel(const float* __restrict__ K, const float* __restrict__ Q,
                           const float* __restrict__ V) {
  constexpr int N4 = (int)(TELEM / 4);
  const int stride = gridDim.x * blockDim.x;
  const float qscale = 0.088388347648318447f;  // 1/sqrt(128)
  for (int idx = blockIdx.x * blockDim.x + threadIdx.x; idx < 3 * N4; idx += stride) {
    const int t = idx / N4, e = idx - t * N4;
    const float* src = (t == 0) ? K : ((t == 1) ? Q : V);
    float4 v = ((const float4*)src)[e];
    if (t == 1) {
      v.x *= qscale; v.y *= qscale; v.z *= qscale; v.w *= qscale;
    }
    unsigned h0, l0, h1, l1;
    splitpk(v.x, v.y, h0, l0);
    splitpk(v.z, v.w, h1, l1);
    ((uint2*)g_hi[t])[e] = make_uint2(h0, h1);
    ((uint2*)g_lo[t])[e] = make_uint2(l0, l1);
  }
}

// ---- Pass 2: flash attention chunk kernel ----
__global__ __launch_bounds__(NTH, 2)
void fa_mma_kernel() {
  extern __shared__ char sm[];
  const unsigned smb = smem_u32(sm);
  const int tid = threadIdx.x, lane = tid & 31, w = tid >> 5;
  const int g = lane >> 3, l7 = lane & 7, quad = lane >> 2, qlane = lane & 3;

  // decode chunk: batches interleaved, q-tiles descending (LPT order)
  const int b = blockIdx.x & 3;
  int ci = blockIdx.x >> 2;
  int qt = 0, c = 0;
  for (int t = 63; t >= 0; --t) {
    const int n = (t >> 4) + 1;
    if (ci < n) { qt = t; c = ci; break; }
    ci -= n;
  }
  const int q0 = qt * BQ;
  const int ktb = c * CHUNK32;                   // in 32-key tiles
  const int kte = min(ktb + CHUNK32, 2 * qt + 2);

  const __nv_bfloat16* Kh = g_hi[0] + (size_t)b * SEQ * HD;
  const __nv_bfloat16* Kl = g_lo[0] + (size_t)b * SEQ * HD;
  const __nv_bfloat16* Qh = g_hi[1] + (size_t)b * SEQ * HD;
  const __nv_bfloat16* Ql = g_lo[1] + (size_t)b * SEQ * HD;
  const __nv_bfloat16* Vh = g_hi[2] + (size_t)b * SEQ * HD;
  const __nv_bfloat16* Vl = g_lo[2] + (size_t)b * SEQ * HD;

  // ldmatrix per-lane row/chunk offsets
  const int rowAl = ((g & 1) << 3) + l7;         // A (Q)
  const int cAoff = g >> 1;
  const int rowBl = (((g >> 1) & 1) << 3) + l7;  // B (K)
  const int cBoff = g & 1;
  const int rowVl = ((g & 1) << 3) + l7;         // V (trans)
  const int cVoff = g >> 1;

  copy_tile64(sm, SM_QH, Qh + (size_t)q0 * HD, tid);
  copy_tile64(sm, SM_QL, Ql + (size_t)q0 * HD, tid);

  // prologue: async-load first 32-key tile into buffer 0
  unsigned buf = 0;
  {
    const size_t nk = (size_t)ktb * BK * HD;
    const unsigned nb = smb + SM_BUF0;
    copy_tile_async32(nb, Kh + nk, tid);
    copy_tile_async32(nb + 8192u, Kl + nk, tid);
    copy_tile_async32(nb + 16384u, Vh + nk, tid);
    copy_tile_async32(nb + 24576u, Vl + nk, tid);
    asm volatile("cp.async.commit_group;" ::: "memory");
  }

  float o[16][4];
#pragma unroll
  for (int n = 0; n < 16; ++n)
#pragma unroll
    for (int e = 0; e < 4; ++e) o[n][e] = 0.f;
  float m0 = -CUDART_INF_F, m1 = -CUDART_INF_F, l0 = 0.f, l1 = 0.f;

  for (int kt = ktb; kt < kte; ++kt) {
    asm volatile("cp.async.wait_group 0;" ::: "memory");
    __syncthreads();  // current buffer ready; all warps done with the OTHER buffer

    if (kt + 1 < kte) {  // prefetch next tile into the other buffer (now free)
      const unsigned nb = smb + SM_BUF0 + (buf ^ 1u) * (unsigned)BUF_STRIDE;
      const size_t nk = (size_t)(kt + 1) * BK * HD;
      copy_tile_async32(nb, Kh + nk, tid);
      copy_tile_async32(nb + 8192u, Kl + nk, tid);
      copy_tile_async32(nb + 16384u, Vh + nk, tid);
      copy_tile_async32(nb + 24576u, Vl + nk, tid);
      asm volatile("cp.async.commit_group;" ::: "memory");
    }
    const unsigned kb = smb + SM_BUF0 + buf * (unsigned)BUF_STRIDE;
    buf ^= 1u;

    // ---- S = Qh*Kh + Qh*Kl + Ql*Kh (Q pre-scaled); 16q x 32k per warp ----
    float s[4][4];
#pragma unroll
    for (int n = 0; n < 4; ++n)
#pragma unroll
      for (int e = 0; e < 4; ++e) s[n][e] = 0.f;

    const unsigned arow = smb + SM_QH + (unsigned)(16 * w + rowAl) * 256u;
#pragma unroll
    for (int ks = 0; ks < 8; ++ks) {
      unsigned ah[4], al[4];
      const unsigned ca = (unsigned)(((2 * ks + cAoff) ^ l7) << 4);
      ldsm4(ah, arow + ca);
      ldsm4(al, arow + 16384u + ca);
      const unsigned cb = (unsigned)(((2 * ks + cBoff) ^ l7) << 4);
#pragma unroll
      for (int t = 0; t < 2; ++t) {
        unsigned bh[4], bl[4];
        const unsigned kaddr = kb + (unsigned)(t * 16 + rowBl) * 256u + cb;
        ldsm4(bh, kaddr);
        ldsm4(bl, kaddr + 8192u);
        mma16816(s[2 * t], ah, bh[0], bh[1]);
        mma16816(s[2 * t + 1], ah, bh[2], bh[3]);
        mma16816(s[2 * t], ah, bl[0], bl[1]);
        mma16816(s[2 * t + 1], ah, bl[2], bl[3]);
        mma16816(s[2 * t], al, bh[0], bh[1]);
        mma16816(s[2 * t + 1], al, bh[2], bh[3]);
      }
    }

    // ---- causal mask: key offset = (kt-2qt)*32 (last two tiles only) ----
    if (kt >= 2 * qt) {
      const int off = (kt - 2 * qt) * 32;
      const int r0l = 16 * w + quad;
#pragma unroll
      for (int n = 0; n < 4; ++n) {
        const int c0 = off + 8 * n + 2 * qlane;
        if (c0 > r0l) s[n][0] = -CUDART_INF_F;
        if (c0 + 1 > r0l) s[n][1] = -CUDART_INF_F;
        if (c0 > r0l + 8) s[n][2] = -CUDART_INF_F;
        if (c0 + 1 > r0l + 8) s[n][3] = -CUDART_INF_F;
      }
    }

    // ---- online softmax (quad = 4 lanes sharing a row; warp-local) ----
    float mx0 = -CUDART_INF_F, mx1 = -CUDART_INF_F;
#pragma unroll
    for (int n = 0; n < 4; ++n) {
      mx0 = fmaxf(mx0, fmaxf(s[n][0], s[n][1]));
      mx1 = fmaxf(mx1, fmaxf(s[n][2], s[n][3]));
    }
    mx0 = fmaxf(mx0, __shfl_xor_sync(0xffffffffu, mx0, 1));
    mx0 = fmaxf(mx0, __shfl_xor_sync(0xffffffffu, mx0, 2));
    mx1 = fmaxf(mx1, __shfl_xor_sync(0xffffffffu, mx1, 1));
    mx1 = fmaxf(mx1, __shfl_xor_sync(0xffffffffu, mx1, 2));
    const float m0n = fmaxf(m0, mx0), m1n = fmaxf(m1, mx1);
    const float a0 = __expf(m0 - m0n), a1 = __expf(m1 - m1n);
    float s0 = 0.f, s1 = 0.f;
#pragma unroll
    for (int n = 0; n < 4; ++n) {
      s[n][0] = __expf(s[n][0] - m0n);
      s[n][1] = __expf(s[n][1] - m0n);
      s[n][2] = __expf(s[n][2] - m1n);
      s[n][3] = __expf(s[n][3] - m1n);
      s0 += s[n][0] + s[n][1];
      s1 += s[n][2] + s[n][3];
    }
    s0 += __shfl_xor_sync(0xffffffffu, s0, 1);
    s0 += __shfl_xor_sync(0xffffffffu, s0, 2);
    s1 += __shfl_xor_sync(0xffffffffu, s1, 1);
    s1 += __shfl_xor_sync(0xffffffffu, s1, 2);
    l0 = l0 * a0 + s0;
    l1 = l1 * a1 + s1;
    m0 = m0n;
    m1 = m1n;

#pragma unroll
    for (int n = 0; n < 16; ++n) {
      o[n][0] *= a0;
      o[n][1] *= a0;
      o[n][2] *= a1;
      o[n][3] *= a1;
    }

    // ---- O += Ph*Vh + Ph*Vl + Pl*Vh ----
#pragma unroll
    for (int ks = 0; ks < 2; ++ks) {
      unsigned ah[4], al[4];
      splitpk(s[2 * ks][0], s[2 * ks][1], ah[0], al[0]);
      splitpk(s[2 * ks][2], s[2 * ks][3], ah[1], al[1]);
      splitpk(s[2 * ks + 1][0], s[2 * ks + 1][1], ah[2], al[2]);
      splitpk(s[2 * ks + 1][2], s[2 * ks + 1][3], ah[3], al[3]);
#pragma unroll
      for (int u = 0; u < 8; ++u) {
        unsigned vh[4], vl[4];
        const unsigned vaddr = kb + 16384u + (unsigned)(16 * ks + rowVl) * 256u +
                               (unsigned)(((2 * u + cVoff) ^ l7) << 4);
        ldsm4t(vh, vaddr);
        ldsm4t(vl, vaddr + 8192u);
        mma16816(o[2 * u], ah, vh[0], vh[1]);
        mma16816(o[2 * u + 1], ah, vh[2], vh[3]);
        mma16816(o[2 * u], ah, vl[0], vl[1]);
        mma16816(o[2 * u + 1], ah, vl[2], vl[3]);
        mma16816(o[2 * u], al, vh[0], vh[1]);
        mma16816(o[2 * u + 1], al, vh[2], vh[3]);
      }
    }
  }  // kt

  // ---- epilogue: write unnormalized partial O + (m, l) to scratch ----
  const int slot = ((b * 64 + qt) << 2) + c;
  float* op = g_opart[slot];
  const int r0l = 16 * w + quad;
#pragma unroll
  for (int n = 0; n < 16; ++n) {
    const int col = 8 * n + 2 * qlane;
    *(float2*)(op + r0l * HD + col) = make_float2(o[n][0], o[n][1]);
    *(float2*)(op + (r0l + 8) * HD + col) = make_float2(o[n][2], o[n][3]);
  }
  if (qlane == 0) {
    g_mlpart[slot][r0l] = make_float2(m0, l0);
    g_mlpart[slot][r0l + 8] = make_float2(m1, l1);
  }
}

// ---- Pass 3: combine partials (one warp per output row) ----
__global__ __launch_bounds__(256)
void combine_kernel(float* __restrict__ Og) {
  const int row = (blockIdx.x * blockDim.x + threadIdx.x) >> 5;  // 0..16383
  const int lane = threadIdx.x & 31;
  const int b = row >> 12, r = row & 4095;
  const int qt = r >> 6, rr = r & 63;
  const int nc = (qt >> 4) + 1;
  const int slot0 = (b * 64 + qt) << 2;

  float m[4], l[4];
  float mstar = -CUDART_INF_F;
#pragma unroll
  for (int c = 0; c < 4; ++c) {
    if (c < nc) {
      const float2 ml = g_mlpart[slot0 + c][rr];
      m[c] = ml.x;
      l[c] = ml.y;
      mstar = fmaxf(mstar, ml.x);
    }
  }
  float denom = 0.f, wgt[4];
#pragma unroll
  for (int c = 0; c < 4; ++c) {
    if (c < nc) {
      wgt[c] = __expf(m[c] - mstar);
      denom += wgt[c] * l[c];
    }
  }
  float4 acc = make_float4(0.f, 0.f, 0.f, 0.f);
#pragma unroll
  for (int c = 0; c < 4; ++c) {
    if (c < nc) {
      const float4 v = *(const float4*)(g_opart[slot0 + c] + rr * HD + lane * 4);
      acc.x += wgt[c] * v.x;
      acc.y += wgt[c] * v.y;
      acc.z += wgt[c] * v.z;
      acc.w += wgt[c] * v.w;
    }
  }
  const float inv = 1.f / denom;
  acc.x *= inv; acc.y *= inv; acc.z *= inv; acc.w *= inv;
  *(float4*)(Og + ((size_t)b * SEQ + r) * HD + lane * 4) = acc;
}

extern "C" void kernel_launch(void* const* d_in, const int* in_sizes, int n_in,
                              void* d_out, int out_size) {
  const float* K = (const float*)d_in[0];
  const float* Q = (const float*)d_in[1];
  const float* V = (const float*)d_in[2];
  float* O = (float*)d_out;

  cvt_kernel<<<2048, 256>>>(K, Q, V);

  cudaFuncSetAttribute(fa_mma_kernel, cudaFuncAttributeMaxDynamicSharedMemorySize,
                       SMEM_BYTES);
  // chunks per batch: sum over qt of (qt>>4)+1 = 160; batches interleaved.
  fa_mma_kernel<<<160 * NB, NTH, SMEM_BYTES>>>();

  combine_kernel<<<(NB * SEQ * 32) / 256, 256>>>(O);
}

// round 15
// speedup vs baseline: 1.1189x; 1.0190x over previous
#include <cuda_runtime.h>
#include <cuda_bf16.h>
#include <math_constants.h>
#include <cstdint>

// Causal attention B=4 L=4096 D=128 fp32 via mma.sync bf16 hi/lo split (3-term).
// Pass 1: cvt fp32 -> bf16 hi/lo (Q pre-scaled by 1/sqrt(128)).
// Pass 2: FA2 split-K. BQ=64, 4 warps, 96KB smem -> 2 CTAs/SM. Single K/V
//   buffer but SPLIT REFILL pipeline: K(kt+1) loaded right after the S-phase
//   (overlaps softmax+PV), V(kt+1) after the PV-phase (overlaps next S),
//   sequenced with cp.async group FIFO waits. Chunks of <=16 k-tiles, LPT
//   order, 640 CTAs. Chunks covering a whole q-tile (qt<16) write normalized
//   output directly; others write partials (O, m, l) to scratch.
// Pass 3: combine kernel merges partials for qt>=16 rows only.

namespace {
constexpr int SEQ = 4096, HD = 128, NB = 4;
constexpr int BQ = 64, BK = 64;
constexpr int NTH = 128;
constexpr int CHUNK = 16;  // k-tiles per chunk
constexpr size_t TELEM = (size_t)NB * SEQ * HD;

// smem: Q hi/lo 32KB + single K/V buffer 64KB = 96KB (2 CTAs/SM)
constexpr int SM_QH = 0, SM_QL = 16384, SM_KH = 32768, SM_KL = 49152,
              SM_VH = 65536, SM_VL = 81920, SMEM_BYTES = 98304;

// chunks per q-tile: qt/16+1 (1..4). slots = (b*64+qt)*4 + c.
constexpr int NSLOT = NB * 64 * 4;  // 1024
}  // namespace

__device__ __nv_bfloat16 g_hi[3][TELEM];  // 0=K, 1=Q(scaled), 2=V
__device__ __nv_bfloat16 g_lo[3][TELEM];
__device__ float g_opart[NSLOT][BQ * HD];   // unnormalized partial O
__device__ float2 g_mlpart[NSLOT][BQ];      // per-row (m, l)

namespace {

__device__ __forceinline__ unsigned smem_u32(const void* p) {
  unsigned a;
  asm("{ .reg .u64 t; cvta.to.shared.u64 t, %1; cvt.u32.u64 %0, t; }" : "=r"(a) : "l"(p));
  return a;
}

__device__ __forceinline__ void splitpk(float x, float y, unsigned& hi, unsigned& lo) {
  __nv_bfloat162 h = __floats2bfloat162_rn(x, y);
  hi = *reinterpret_cast<unsigned*>(&h);
  __nv_bfloat162 l = __floats2bfloat162_rn(x - __bfloat162float(h.x),
                                           y - __bfloat162float(h.y));
  lo = *reinterpret_cast<unsigned*>(&l);
}

__device__ __forceinline__ void ldsm4(unsigned* r, unsigned a) {
  asm volatile("ldmatrix.sync.aligned.m8n8.x4.shared.b16 {%0,%1,%2,%3}, [%4];"
               : "=r"(r[0]), "=r"(r[1]), "=r"(r[2]), "=r"(r[3]) : "r"(a));
}

__device__ __forceinline__ void ldsm4t(unsigned* r, unsigned a) {
  asm volatile("ldmatrix.sync.aligned.m8n8.x4.trans.shared.b16 {%0,%1,%2,%3}, [%4];"
               : "=r"(r[0]), "=r"(r[1]), "=r"(r[2]), "=r"(r[3]) : "r"(a));
}

__device__ __forceinline__ void mma16816(float* d, const unsigned* a, unsigned b0,
                                         unsigned b1) {
  asm volatile(
      "mma.sync.aligned.m16n8k16.row.col.f32.bf16.bf16.f32 "
      "{%0,%1,%2,%3}, {%4,%5,%6,%7}, {%8,%9}, {%0,%1,%2,%3};"
      : "+f"(d[0]), "+f"(d[1]), "+f"(d[2]), "+f"(d[3])
      : "r"(a[0]), "r"(a[1]), "r"(a[2]), "r"(a[3]), "r"(b0), "r"(b1));
}

// Synchronous copy of a 64x128 bf16 tile into swizzled smem (128 threads).
__device__ __forceinline__ void copy_tile(char* sm, int off, const __nv_bfloat16* g,
                                          int tid) {
  const uint4* g4 = (const uint4*)g;
#pragma unroll
  for (int it = 0; it < 8; ++it) {
    const int c16 = it * 128 + tid;
    const int row = c16 >> 4, c = c16 & 15;
    const uint4 v = g4[c16];
    *(uint4*)(sm + off + row * 256 + ((c ^ (row & 7)) << 4)) = v;
  }
}

// Async copy of a 64x128 bf16 tile into swizzled smem (128 threads).
__device__ __forceinline__ void copy_tile_async(unsigned dst, const __nv_bfloat16* g,
                                                int tid) {
  const uint4* g4 = (const uint4*)g;
#pragma unroll
  for (int it = 0; it < 8; ++it) {
    const int c16 = it * 128 + tid;
    const int row = c16 >> 4, c = c16 & 15;
    const unsigned a = dst + row * 256 + ((c ^ (row & 7)) << 4);
    asm volatile("cp.async.cg.shared.global [%0], [%1], 16;" :: "r"(a), "l"(g4 + c16)
                 : "memory");
  }
}
}  // namespace

// ---- Pass 1: fp32 -> bf16 hi/lo (Q scaled by 1/sqrt(HD)) ----
__global__ void cvt_kernel(const float* __restrict__ K, const float* __restrict__ Q,
                           const float* __restrict__ V) {
  constexpr int N4 = (int)(TELEM / 4);
  const int stride = gridDim.x * blockDim.x;
  const float qscale = 0.088388347648318447f;  // 1/sqrt(128)
  for (int idx = blockIdx.x * blockDim.x + threadIdx.x; idx < 3 * N4; idx += stride) {
    const int t = idx / N4, e = idx - t * N4;
    const float* src = (t == 0) ? K : ((t == 1) ? Q : V);
    float4 v = ((const float4*)src)[e];
    if (t == 1) {
      v.x *= qscale; v.y *= qscale; v.z *= qscale; v.w *= qscale;
    }
    unsigned h0, l0, h1, l1;
    splitpk(v.x, v.y, h0, l0);
    splitpk(v.z, v.w, h1, l1);
    ((uint2*)g_hi[t])[e] = make_uint2(h0, h1);
    ((uint2*)g_lo[t])[e] = make_uint2(l0, l1);
  }
}

// ---- Pass 2: flash attention chunk kernel ----
__global__ __launch_bounds__(NTH, 2)
void fa_mma_kernel(float* __restrict__ Og) {
  extern __shared__ char sm[];
  const unsigned smb = smem_u32(sm);
  const int tid = threadIdx.x, lane = tid & 31, w = tid >> 5;
  const int g = lane >> 3, l7 = lane & 7, quad = lane >> 2, qlane = lane & 3;

  // decode chunk: batches interleaved, q-tiles descending (LPT order)
  const int b = blockIdx.x & 3;
  int ci = blockIdx.x >> 2;
  int qt = 0, c = 0;
  for (int t = 63; t >= 0; --t) {
    const int n = (t >> 4) + 1;
    if (ci < n) { qt = t; c = ci; break; }
    ci -= n;
  }
  const int q0 = qt * BQ;
  const int ktb = c * CHUNK;
  const int kte = min(ktb + CHUNK, qt + 1);

  const __nv_bfloat16* Kh = g_hi[0] + (size_t)b * SEQ * HD;
  const __nv_bfloat16* Kl = g_lo[0] + (size_t)b * SEQ * HD;
  const __nv_bfloat16* Qh = g_hi[1] + (size_t)b * SEQ * HD;
  const __nv_bfloat16* Ql = g_lo[1] + (size_t)b * SEQ * HD;
  const __nv_bfloat16* Vh = g_hi[2] + (size_t)b * SEQ * HD;
  const __nv_bfloat16* Vl = g_lo[2] + (size_t)b * SEQ * HD;

  // ldmatrix per-lane row/chunk offsets
  const int rowAl = ((g & 1) << 3) + l7;         // A (Q)
  const int cAoff = g >> 1;
  const int rowBl = (((g >> 1) & 1) << 3) + l7;  // B (K)
  const int cBoff = g & 1;
  const int rowVl = ((g & 1) << 3) + l7;         // V (trans)
  const int cVoff = g >> 1;

  copy_tile(sm, SM_QH, Qh + (size_t)q0 * HD, tid);
  copy_tile(sm, SM_QL, Ql + (size_t)q0 * HD, tid);

  // prologue: K group then V group for tile ktb (two cp.async groups in FIFO)
  {
    const size_t nk = (size_t)ktb * BK * HD;
    copy_tile_async(smb + SM_KH, Kh + nk, tid);
    copy_tile_async(smb + SM_KL, Kl + nk, tid);
    asm volatile("cp.async.commit_group;" ::: "memory");
    copy_tile_async(smb + SM_VH, Vh + nk, tid);
    copy_tile_async(smb + SM_VL, Vl + nk, tid);
    asm volatile("cp.async.commit_group;" ::: "memory");
  }

  float o[16][4];
#pragma unroll
  for (int n = 0; n < 16; ++n)
#pragma unroll
    for (int e = 0; e < 4; ++e) o[n][e] = 0.f;
  float m0 = -CUDART_INF_F, m1 = -CUDART_INF_F, l0 = 0.f, l1 = 0.f;

  for (int kt = ktb; kt < kte; ++kt) {
    // K(kt) is the oldest outstanding group; V(kt) may still be in flight.
    asm volatile("cp.async.wait_group 1;" ::: "memory");
    __syncthreads();  // K tile visible to all warps

    // ---- S = Qh*Kh + Qh*Kl + Ql*Kh (Q pre-scaled) ----
    float s[8][4];
#pragma unroll
    for (int n = 0; n < 8; ++n)
#pragma unroll
      for (int e = 0; e < 4; ++e) s[n][e] = 0.f;

    const unsigned arow = smb + SM_QH + (unsigned)(16 * w + rowAl) * 256u;
#pragma unroll
    for (int ks = 0; ks < 8; ++ks) {
      unsigned ah[4], al[4];
      const unsigned ca = (unsigned)(((2 * ks + cAoff) ^ l7) << 4);
      ldsm4(ah, arow + ca);
      ldsm4(al, arow + 16384u + ca);
      const unsigned cb = (unsigned)(((2 * ks + cBoff) ^ l7) << 4);
#pragma unroll
      for (int t = 0; t < 4; ++t) {
        unsigned bh[4], bl[4];
        const unsigned kaddr = smb + SM_KH + (unsigned)(t * 16 + rowBl) * 256u + cb;
        ldsm4(bh, kaddr);
        ldsm4(bl, kaddr + 16384u);
        mma16816(s[2 * t], ah, bh[0], bh[1]);
        mma16816(s[2 * t + 1], ah, bh[2], bh[3]);
        mma16816(s[2 * t], ah, bl[0], bl[1]);
        mma16816(s[2 * t + 1], ah, bl[2], bl[3]);
        mma16816(s[2 * t], al, bh[0], bh[1]);
        mma16816(s[2 * t + 1], al, bh[2], bh[3]);
      }
    }

    // K reads complete -> refill K(kt+1); load overlaps softmax + PV below.
    __syncthreads();
    const bool refill = (kt + 1 < kte);
    if (refill) {
      const size_t nk = (size_t)(kt + 1) * BK * HD;
      copy_tile_async(smb + SM_KH, Kh + nk, tid);
      copy_tile_async(smb + SM_KL, Kl + nk, tid);
      asm volatile("cp.async.commit_group;" ::: "memory");
    }

    // ---- causal mask on the diagonal tile ----
    if (kt == qt) {
      const int r0l = 16 * w + quad;
#pragma unroll
      for (int n = 0; n < 8; ++n) {
        const int c0 = 8 * n + 2 * qlane;
        if (c0 > r0l) s[n][0] = -CUDART_INF_F;
        if (c0 + 1 > r0l) s[n][1] = -CUDART_INF_F;
        if (c0 > r0l + 8) s[n][2] = -CUDART_INF_F;
        if (c0 + 1 > r0l + 8) s[n][3] = -CUDART_INF_F;
      }
    }

    // ---- online softmax (quad = 4 lanes sharing a row; warp-local) ----
    float mx0 = -CUDART_INF_F, mx1 = -CUDART_INF_F;
#pragma unroll
    for (int n = 0; n < 8; ++n) {
      mx0 = fmaxf(mx0, fmaxf(s[n][0], s[n][1]));
      mx1 = fmaxf(mx1, fmaxf(s[n][2], s[n][3]));
    }
    mx0 = fmaxf(mx0, __shfl_xor_sync(0xffffffffu, mx0, 1));
    mx0 = fmaxf(mx0, __shfl_xor_sync(0xffffffffu, mx0, 2));
    mx1 = fmaxf(mx1, __shfl_xor_sync(0xffffffffu, mx1, 1));
    mx1 = fmaxf(mx1, __shfl_xor_sync(0xffffffffu, mx1, 2));
    const float m0n = fmaxf(m0, mx0), m1n = fmaxf(m1, mx1);
    const float a0 = __expf(m0 - m0n), a1 = __expf(m1 - m1n);
    float s0 = 0.f, s1 = 0.f;
#pragma unroll
    for (int n = 0; n < 8; ++n) {
      s[n][0] = __expf(s[n][0] - m0n);
      s[n][1] = __expf(s[n][1] - m0n);
      s[n][2] = __expf(s[n][2] - m1n);
      s[n][3] = __expf(s[n][3] - m1n);
      s0 += s[n][0] + s[n][1];
      s1 += s[n][2] + s[n][3];
    }
    s0 += __shfl_xor_sync(0xffffffffu, s0, 1);
    s0 += __shfl_xor_sync(0xffffffffu, s0, 2);
    s1 += __shfl_xor_sync(0xffffffffu, s1, 1);
    s1 += __shfl_xor_sync(0xffffffffu, s1, 2);
    l0 = l0 * a0 + s0;
    l1 = l1 * a1 + s1;
    m0 = m0n;
    m1 = m1n;

#pragma unroll
    for (int n = 0; n < 16; ++n) {
      o[n][0] *= a0;
      o[n][1] *= a0;
      o[n][2] *= a1;
      o[n][3] *= a1;
    }

    // V(kt): wait leaving the K(kt+1) refill (if any) in flight.
    if (refill) {
      asm volatile("cp.async.wait_group 1;" ::: "memory");
    } else {
      asm volatile("cp.async.wait_group 0;" ::: "memory");
    }
    __syncthreads();  // V tile visible

    // ---- O += Ph*Vh + Ph*Vl + Pl*Vh ----
#pragma unroll
    for (int ks = 0; ks < 4; ++ks) {
      unsigned ah[4], al[4];
      splitpk(s[2 * ks][0], s[2 * ks][1], ah[0], al[0]);
      splitpk(s[2 * ks][2], s[2 * ks][3], ah[1], al[1]);
      splitpk(s[2 * ks + 1][0], s[2 * ks + 1][1], ah[2], al[2]);
      splitpk(s[2 * ks + 1][2], s[2 * ks + 1][3], ah[3], al[3]);
#pragma unroll
      for (int u = 0; u < 8; ++u) {
        unsigned vh[4], vl[4];
        const unsigned vaddr = smb + SM_VH + (unsigned)(16 * ks + rowVl) * 256u +
                               (unsigned)(((2 * u + cVoff) ^ l7) << 4);
        ldsm4t(vh, vaddr);
        ldsm4t(vl, vaddr + 16384u);
        mma16816(o[2 * u], ah, vh[0], vh[1]);
        mma16816(o[2 * u + 1], ah, vh[2], vh[3]);
        mma16816(o[2 * u], ah, vl[0], vl[1]);
        mma16816(o[2 * u + 1], ah, vl[2], vl[3]);
        mma16816(o[2 * u], al, vh[0], vh[1]);
        mma16816(o[2 * u + 1], al, vh[2], vh[3]);
      }
    }

    if (refill) {  // V reads complete -> refill V(kt+1); overlaps next S-phase
      __syncthreads();
      const size_t nk = (size_t)(kt + 1) * BK * HD;
      copy_tile_async(smb + SM_VH, Vh + nk, tid);
      copy_tile_async(smb + SM_VL, Vl + nk, tid);
      asm volatile("cp.async.commit_group;" ::: "memory");
    }
  }  // kt

  const int r0l = 16 * w + quad;
  if (qt < 16) {
    // single-chunk q-tile: write normalized output directly
    const float i0 = 1.f / l0, i1 = 1.f / l1;
    float* og = Og + ((size_t)b * SEQ + q0 + r0l) * HD;
#pragma unroll
    for (int n = 0; n < 16; ++n) {
      const int col = 8 * n + 2 * qlane;
      *(float2*)(og + col) = make_float2(o[n][0] * i0, o[n][1] * i0);
      *(float2*)(og + 8 * HD + col) = make_float2(o[n][2] * i1, o[n][3] * i1);
    }
  } else {
    // write unnormalized partial O + (m, l) to scratch
    const int slot = ((b * 64 + qt) << 2) + c;
    float* op = g_opart[slot];
#pragma unroll
    for (int n = 0; n < 16; ++n) {
      const int col = 8 * n + 2 * qlane;
      *(float2*)(op + r0l * HD + col) = make_float2(o[n][0], o[n][1]);
      *(float2*)(op + (r0l + 8) * HD + col) = make_float2(o[n][2], o[n][3]);
    }
    if (qlane == 0) {
      g_mlpart[slot][r0l] = make_float2(m0, l0);
      g_mlpart[slot][r0l + 8] = make_float2(m1, l1);
    }
  }
}

// ---- Pass 3: combine partials for qt>=16 rows (one warp per output row) ----
__global__ __launch_bounds__(256)
void combine_kernel(float* __restrict__ Og) {
  const int wid = (blockIdx.x * blockDim.x + threadIdx.x) >> 5;  // 0..NB*3072-1
  const int lane = threadIdx.x & 31;
  const int b = wid / 3072;
  const int r = 1024 + (wid - b * 3072);  // rows with qt>=16
  const int qt = r >> 6, rr = r & 63;
  const int nc = (qt >> 4) + 1;  // 2..4
  const int slot0 = (b * 64 + qt) << 2;

  float m[4], l[4];
  float mstar = -CUDART_INF_F;
#pragma unroll
  for (int c = 0; c < 4; ++c) {
    if (c < nc) {
      const float2 ml = g_mlpart[slot0 + c][rr];
      m[c] = ml.x;
      l[c] = ml.y;
      mstar = fmaxf(mstar, ml.x);
    }
  }
  float denom = 0.f, wgt[4];
#pragma unroll
  for (int c = 0; c < 4; ++c) {
    if (c < nc) {
      wgt[c] = __expf(m[c] - mstar);
      denom += wgt[c] * l[c];
    }
  }
  float4 acc = make_float4(0.f, 0.f, 0.f, 0.f);
#pragma unroll
  for (int c = 0; c < 4; ++c) {
    if (c < nc) {
      const float4 v = *(const float4*)(g_opart[slot0 + c] + rr * HD + lane * 4);
      acc.x += wgt[c] * v.x;
      acc.y += wgt[c] * v.y;
      acc.z += wgt[c] * v.z;
      acc.w += wgt[c] * v.w;
    }
  }
  const float inv = 1.f / denom;
  acc.x *= inv; acc.y *= inv; acc.z *= inv; acc.w *= inv;
  *(float4*)(Og + ((size_t)b * SEQ + r) * HD + lane * 4) = acc;
}

extern "C" void kernel_launch(void* const* d_in, const int* in_sizes, int n_in,
                              void* d_out, int out_size) {
  const float* K = (const float*)d_in[0];
  const float* Q = (const float*)d_in[1];
  const float* V = (const float*)d_in[2];
  float* O = (float*)d_out;

  cvt_kernel<<<2048, 256>>>(K, Q, V);

  cudaFuncSetAttribute(fa_mma_kernel, cudaFuncAttributeMaxDynamicSharedMemorySize,
                       SMEM_BYTES);
  // chunks per batch: sum over qt of (qt>>4)+1 = 160; batches interleaved.
  fa_mma_kernel<<<160 * NB, NTH, SMEM_BYTES>>>(O);

  // combine only rows with qt>=16: NB * 3072 rows, one warp each.
  combine_kernel<<<(NB * 3072 * 32) / 256, 256>>>(O);
}